// round 1
// baseline (speedup 1.0000x reference)
#include <cuda_runtime.h>

#define BB 64
#define CC 32
#define HHW 16
#define KK 4096
#define NPIX (BB*CC*HHW*HHW)   // 524288
#define MAXTOK 16384

__device__ float g_zrest[NPIX];
__device__ float g_zflat[MAXTOK*CC];
__device__ float g_zsq[MAXTOK];
__device__ float g_wsq[KK];
__device__ float g_pd[32768];
__device__ int   g_pi[32768];
__device__ int   g_tok[MAXTOK];

// ---------------- init: z_rest = z_enc ----------------
__global__ void k_init(const float* __restrict__ z) {
    int i = blockIdx.x * 256 + threadIdx.x;
    g_zrest[i] = z[i];
}

// ---------------- wsq[k] = sum(emb[k]^2) (sequential, round-to-nearest) ----
__global__ void k_wsq(const float* __restrict__ w) {
    int r = blockIdx.x * 256 + threadIdx.x;   // 0..4095
    const float* p = w + r * 32;
    float s = 0.f;
#pragma unroll
    for (int c = 0; c < 32; c++) s = __fadd_rn(s, __fmul_rn(p[c], p[c]));
    g_wsq[r] = s;
}

// ---------------- prep: area-downsample z_rest -> zflat[t][c], zsq[t] -------
// warp per token, lane = channel
__global__ void k_prep(int pn) {
    int warp = threadIdx.x >> 5, lane = threadIdx.x & 31;
    int t = blockIdx.x * 8 + warp;
    int pn2 = pn * pn;
    int b = t / pn2, r = t % pn2;
    int y = r / pn, x = r % pn;
    int sub = 16 / pn;
    float inv = 1.f / (float)(sub * sub);   // exact power of two
    const float* base = g_zrest + (((b * 32 + lane) * 16 + y * sub) * 16 + x * sub);
    float s = 0.f;
    for (int dy = 0; dy < sub; dy++)
        for (int dx = 0; dx < sub; dx++)
            s = __fadd_rn(s, base[dy * 16 + dx]);
    float zd = __fmul_rn(s, inv);
    g_zflat[t * 32 + lane] = zd;
    float q = __fmul_rn(zd, zd);
#pragma unroll
    for (int off = 16; off; off >>= 1)
        q = __fadd_rn(q, __shfl_xor_sync(0xffffffffu, q, off));
    if (lane == 0) g_zsq[t] = q;
}

// ---------------- dist+argmin: 64 tokens x 64 codes register tile -----------
// grid.x = tokens/64, grid.y = KSPLIT; each CTA loops `iters` chunks of 64 codes.
__global__ void __launch_bounds__(256) k_dist(const float* __restrict__ emb,
                                              int codesPerSplit, int iters) {
    __shared__ float zs[32][64];
    __shared__ float es[32][64];
    __shared__ float ws[64];
    int tid = threadIdx.x;
    int tx = tid & 15, ty = tid >> 4;
    int tb = blockIdx.x * 64;

    // stage z tile (transpose to c-major)
    {
        int tok = tb + (tid >> 2);
        int part = tid & 3;
        const float4* p = (const float4*)(g_zflat + tok * 32 + part * 8);
        float4 a = p[0], b4 = p[1];
        int c0 = part * 8, tt = tid >> 2;
        zs[c0+0][tt]=a.x;  zs[c0+1][tt]=a.y;  zs[c0+2][tt]=a.z;  zs[c0+3][tt]=a.w;
        zs[c0+4][tt]=b4.x; zs[c0+5][tt]=b4.y; zs[c0+6][tt]=b4.z; zs[c0+7][tt]=b4.w;
    }
    float zq[4];
#pragma unroll
    for (int j = 0; j < 4; j++) zq[j] = g_zsq[tb + ty * 4 + j];

    float bd[4]; int bk[4];
#pragma unroll
    for (int j = 0; j < 4; j++) { bd[j] = __int_as_float(0x7f800000); bk[j] = 0; }

    int kbase = blockIdx.y * codesPerSplit;
    for (int it = 0; it < iters; it++) {
        int kb = kbase + it * 64;
        __syncthreads();
        // stage e tile
        {
            int code = kb + (tid >> 2);
            int part = tid & 3;
            const float4* p = (const float4*)(emb + code * 32 + part * 8);
            float4 a = p[0], b4 = p[1];
            int c0 = part * 8, tt = tid >> 2;
            es[c0+0][tt]=a.x;  es[c0+1][tt]=a.y;  es[c0+2][tt]=a.z;  es[c0+3][tt]=a.w;
            es[c0+4][tt]=b4.x; es[c0+5][tt]=b4.y; es[c0+6][tt]=b4.z; es[c0+7][tt]=b4.w;
        }
        if (tid < 64) ws[tid] = g_wsq[kb + tid];
        __syncthreads();

        float acc[4][4];
#pragma unroll
        for (int j = 0; j < 4; j++)
#pragma unroll
            for (int kk = 0; kk < 4; kk++) acc[j][kk] = 0.f;

#pragma unroll
        for (int c = 0; c < 32; c++) {
            float4 zv = *(const float4*)&zs[c][ty * 4];
            float4 ev = *(const float4*)&es[c][tx * 4];
            acc[0][0]=__fmaf_rn(zv.x,ev.x,acc[0][0]); acc[0][1]=__fmaf_rn(zv.x,ev.y,acc[0][1]);
            acc[0][2]=__fmaf_rn(zv.x,ev.z,acc[0][2]); acc[0][3]=__fmaf_rn(zv.x,ev.w,acc[0][3]);
            acc[1][0]=__fmaf_rn(zv.y,ev.x,acc[1][0]); acc[1][1]=__fmaf_rn(zv.y,ev.y,acc[1][1]);
            acc[1][2]=__fmaf_rn(zv.y,ev.z,acc[1][2]); acc[1][3]=__fmaf_rn(zv.y,ev.w,acc[1][3]);
            acc[2][0]=__fmaf_rn(zv.z,ev.x,acc[2][0]); acc[2][1]=__fmaf_rn(zv.z,ev.y,acc[2][1]);
            acc[2][2]=__fmaf_rn(zv.z,ev.z,acc[2][2]); acc[2][3]=__fmaf_rn(zv.z,ev.w,acc[2][3]);
            acc[3][0]=__fmaf_rn(zv.w,ev.x,acc[3][0]); acc[3][1]=__fmaf_rn(zv.w,ev.y,acc[3][1]);
            acc[3][2]=__fmaf_rn(zv.w,ev.z,acc[3][2]); acc[3][3]=__fmaf_rn(zv.w,ev.w,acc[3][3]);
        }
#pragma unroll
        for (int j = 0; j < 4; j++) {
#pragma unroll
            for (int kk = 0; kk < 4; kk++) {
                int k = kb + tx * 4 + kk;     // ascending within thread -> '<' keeps first
                float s1 = __fadd_rn(zq[j], ws[tx * 4 + kk]);
                float d  = __fadd_rn(s1, __fmul_rn(-2.f, acc[j][kk]));
                if (d < bd[j]) { bd[j] = d; bk[j] = k; }
            }
        }
    }
    // reduce across the 16 tx lanes (tie -> lowest code index)
#pragma unroll
    for (int j = 0; j < 4; j++) {
        float d = bd[j]; int k = bk[j];
#pragma unroll
        for (int off = 8; off; off >>= 1) {
            float od = __shfl_xor_sync(0xffffffffu, d, off, 16);
            int   ok = __shfl_xor_sync(0xffffffffu, k, off, 16);
            if (od < d || (od == d && ok < k)) { d = od; k = ok; }
        }
        if (tx == 0) {
            int t = tb + ty * 4 + j;
            g_pd[t * gridDim.y + blockIdx.y] = d;
            g_pi[t * gridDim.y + blockIdx.y] = k;
        }
    }
}

// ---------------- reduce over K-splits ----------------
__global__ void k_red(int N, int KS) {
    int t = blockIdx.x * 256 + threadIdx.x;
    if (t >= N) return;
    float bd = g_pd[t * KS]; int bk = g_pi[t * KS];
    for (int s = 1; s < KS; s++) {
        float d = g_pd[t * KS + s]; int k = g_pi[t * KS + s];
        if (d < bd || (d == bd && k < bk)) { bd = d; bk = k; }
    }
    g_tok[t] = bk;
}

// ---------------- cubic (jax Keys a=-0.5) weights with renormalization ------
template<int PN>
__device__ __forceinline__ void cubw(int o, float* w) {
    if (PN == 1) { w[0] = 1.f; return; }
    float s = __fadd_rn(__fmul_rn(__fadd_rn((float)o, 0.5f), (float)PN / 16.f), -0.5f);
    float tot = 0.f;
#pragma unroll
    for (int i = 0; i < PN; i++) {
        float x = fabsf(s - (float)i);
        float v;
        if (x >= 2.f)      v = 0.f;
        else if (x >= 1.f) v = ((-0.5f * x + 2.5f) * x - 4.f) * x + 2.f;
        else               v = ((1.5f * x - 2.5f) * x) * x + 1.f;
        w[i] = v; tot += v;
    }
#pragma unroll
    for (int i = 0; i < PN; i++) w[i] = w[i] / tot;
}

// ---------------- gather + bicubic up + residual update (levels 0..3) -------
template<int PN>
__global__ void __launch_bounds__(256) k_up(const float* __restrict__ emb,
                                            const float* __restrict__ outPrev,
                                            float* __restrict__ outCur,
                                            int isFirst) {
    __shared__ float ew[PN * PN][32];
    int b = blockIdx.x;
    int tid = threadIdx.x;
    for (int idx = tid; idx < PN * PN * 8; idx += 256) {
        int token = idx >> 3, seg = idx & 7;
        int code = g_tok[b * PN * PN + token];
        float4 v = *(const float4*)(emb + code * 32 + seg * 4);
        *(float4*)&ew[token][seg * 4] = v;
    }
    __syncthreads();
    int y = tid >> 4, x = tid & 15;
    float wy[PN], wx[PN];
    cubw<PN>(y, wy);
    cubw<PN>(x, wx);
#pragma unroll
    for (int c = 0; c < 32; c++) {
        float acc = 0.f;
#pragma unroll
        for (int j = 0; j < PN; j++) {
            float tmp = 0.f;
#pragma unroll
            for (int i = 0; i < PN; i++) tmp += wx[i] * ew[j * PN + i][c];
            acc += wy[j] * tmp;
        }
        int idx = (b * 32 + c) * 256 + y * 16 + x;
        float prev = isFirst ? 0.f : outPrev[idx];
        outCur[idx] = prev + acc;
        g_zrest[idx] = g_zrest[idx] - acc;
    }
}

// ---------------- last level: plain gather + accumulate ----------------
__global__ void k_up_last(const float* __restrict__ emb,
                          const float* __restrict__ outPrev,
                          float* __restrict__ outCur) {
    int b = blockIdx.x, tid = threadIdx.x;
    int tok = g_tok[b * 256 + tid];
    const float* e = emb + tok * 32;
#pragma unroll
    for (int c = 0; c < 32; c++) {
        int idx = (b * 32 + c) * 256 + tid;
        outCur[idx] = outPrev[idx] + e[c];
    }
}

extern "C" void kernel_launch(void* const* d_in, const int* in_sizes, int n_in,
                              void* d_out, int out_size) {
    const float* z = (const float*)d_in[0];     // z_enc [64,32,16,16]
    const float* w = (const float*)d_in[1];     // emb_weight [4096,32]
    float* out = (float*)d_out;                 // [5,64,32,16,16]

    k_init<<<NPIX / 256, 256>>>(z);
    k_wsq<<<KK / 256, 256>>>(w);

    const int pns[5]     = {1, 2, 4, 8, 16};
    const int ksplits[5] = {64, 16, 8, 4, 2};

    for (int l = 0; l < 5; l++) {
        int pn = pns[l];
        int N = 64 * pn * pn;
        k_prep<<<N / 8, 256>>>(pn);

        int KS = ksplits[l];
        int codesPerSplit = KK / KS;
        int iters = codesPerSplit / 64;
        dim3 g(N / 64, KS);
        k_dist<<<g, 256>>>(w, codesPerSplit, iters);
        k_red<<<(N + 255) / 256, 256>>>(N, KS);

        float* cur = out + (size_t)l * NPIX;
        const float* prev = (l == 0) ? out : out + (size_t)(l - 1) * NPIX;
        if      (l == 0) k_up<1><<<64, 256>>>(w, prev, cur, 1);
        else if (l == 1) k_up<2><<<64, 256>>>(w, prev, cur, 0);
        else if (l == 2) k_up<4><<<64, 256>>>(w, prev, cur, 0);
        else if (l == 3) k_up<8><<<64, 256>>>(w, prev, cur, 0);
        else             k_up_last<<<64, 256>>>(w, prev, cur);
    }
}

// round 2
// speedup vs baseline: 1.0787x; 1.0787x over previous
#include <cuda_runtime.h>

#define BB 64
#define CC 32
#define KK 4096
#define NPIX (BB*CC*256)       // 524288
#define MAXTOK 16384

__device__ float g_zrest[NPIX];
__device__ float g_zflat[MAXTOK*CC];
__device__ float g_zsq[MAXTOK];
__device__ float g_wsq[KK];
__device__ float g_pd[32768];
__device__ int   g_pi[32768];
__device__ int   g_tok[MAXTOK];

typedef unsigned long long ull;

// ---------------- init: z_rest = z_enc ----------------
__global__ void k_init(const float* __restrict__ z) {
    int i = blockIdx.x * 256 + threadIdx.x;
    g_zrest[i] = z[i];
}

// ---------------- wsq[k] = sum(emb[k]^2) ----------------
__global__ void k_wsq(const float* __restrict__ w) {
    int r = blockIdx.x * 256 + threadIdx.x;
    const float* p = w + r * 32;
    float s = 0.f;
#pragma unroll
    for (int c = 0; c < 32; c++) s = __fadd_rn(s, __fmul_rn(p[c], p[c]));
    g_wsq[r] = s;
}

// ---------------- prep: area-downsample -> zflat, zsq ----------------
__global__ void k_prep(int pn) {
    int warp = threadIdx.x >> 5, lane = threadIdx.x & 31;
    int t = blockIdx.x * 8 + warp;
    int pn2 = pn * pn;
    int b = t / pn2, r = t % pn2;
    int y = r / pn, x = r % pn;
    int sub = 16 / pn;
    float inv = 1.f / (float)(sub * sub);
    const float* base = g_zrest + (((b * 32 + lane) * 16 + y * sub) * 16 + x * sub);
    float s = 0.f;
    for (int dy = 0; dy < sub; dy++)
        for (int dx = 0; dx < sub; dx++)
            s = __fadd_rn(s, base[dy * 16 + dx]);
    float zd = __fmul_rn(s, inv);
    g_zflat[t * 32 + lane] = zd;
    float q = __fmul_rn(zd, zd);
#pragma unroll
    for (int off = 16; off; off >>= 1)
        q = __fadd_rn(q, __shfl_xor_sync(0xffffffffu, q, off));
    if (lane == 0) g_zsq[t] = q;
}

// ---------------- dist+argmin via packed f32x2 FMA -------------------------
// CTA: 128 threads, tile = 64 tokens x 128 codes per iteration.
// Per thread: 8 tokens (as 4 f32x2 token-pairs) x 8 codes = 32 f32x2 accs.
// grid.x = tokens/64, grid.y = KSPLIT.
__global__ void __launch_bounds__(128) k_dist(const float* __restrict__ emb,
                                              int codesPerSplit, int iters) {
    __shared__ float zs[32][64];
    __shared__ float es[32][128];
    __shared__ float ws[128];
    int tid = threadIdx.x;
    int tx = tid & 15, ty = tid >> 4;       // tx: code group, ty: token group
    int tb = blockIdx.x * 64;

    // stage z tile (c-major): 64 tokens x 4 parts = 256 slots
    for (int s = tid; s < 256; s += 128) {
        int tok = s >> 2, part = s & 3;
        const float4* p = (const float4*)(g_zflat + (tb + tok) * 32 + part * 8);
        float4 a = p[0], b4 = p[1];
        int c0 = part * 8;
        zs[c0+0][tok]=a.x;  zs[c0+1][tok]=a.y;  zs[c0+2][tok]=a.z;  zs[c0+3][tok]=a.w;
        zs[c0+4][tok]=b4.x; zs[c0+5][tok]=b4.y; zs[c0+6][tok]=b4.z; zs[c0+7][tok]=b4.w;
    }
    float zq[8];
#pragma unroll
    for (int j = 0; j < 8; j++) zq[j] = g_zsq[tb + ty * 8 + j];

    float bd[8]; int bk[8];
#pragma unroll
    for (int j = 0; j < 8; j++) { bd[j] = __int_as_float(0x7f800000); bk[j] = 0; }

    int kbase = blockIdx.y * codesPerSplit;
    for (int it = 0; it < iters; it++) {
        int kb = kbase + it * 128;
        __syncthreads();
        // stage e tile: 128 codes x 4 parts = 512 slots
        for (int s = tid; s < 512; s += 128) {
            int code = s >> 2, part = s & 3;
            const float4* p = (const float4*)(emb + (kb + code) * 32 + part * 8);
            float4 a = p[0], b4 = p[1];
            int c0 = part * 8;
            es[c0+0][code]=a.x;  es[c0+1][code]=a.y;  es[c0+2][code]=a.z;  es[c0+3][code]=a.w;
            es[c0+4][code]=b4.x; es[c0+5][code]=b4.y; es[c0+6][code]=b4.z; es[c0+7][code]=b4.w;
        }
        ws[tid] = g_wsq[kb + tid];
        __syncthreads();

        ull acc[4][8];
#pragma unroll
        for (int p = 0; p < 4; p++)
#pragma unroll
            for (int k = 0; k < 8; k++) acc[p][k] = 0ull;

#pragma unroll 8
        for (int c = 0; c < 32; c++) {
            // 4 token-pairs, natively packed (adjacent tokens share an f32x2)
            ulonglong2 za = *(const ulonglong2*)&zs[c][ty * 8];
            ulonglong2 zb = *(const ulonglong2*)&zs[c][ty * 8 + 4];
            ull zp[4] = {za.x, za.y, zb.x, zb.y};
            // 8 codes, each duplicated into both f32x2 halves
            float4 e0 = *(const float4*)&es[c][tx * 8];
            float4 e1 = *(const float4*)&es[c][tx * 8 + 4];
            ull ed[8];
            asm("mov.b64 %0, {%1, %1};" : "=l"(ed[0]) : "f"(e0.x));
            asm("mov.b64 %0, {%1, %1};" : "=l"(ed[1]) : "f"(e0.y));
            asm("mov.b64 %0, {%1, %1};" : "=l"(ed[2]) : "f"(e0.z));
            asm("mov.b64 %0, {%1, %1};" : "=l"(ed[3]) : "f"(e0.w));
            asm("mov.b64 %0, {%1, %1};" : "=l"(ed[4]) : "f"(e1.x));
            asm("mov.b64 %0, {%1, %1};" : "=l"(ed[5]) : "f"(e1.y));
            asm("mov.b64 %0, {%1, %1};" : "=l"(ed[6]) : "f"(e1.z));
            asm("mov.b64 %0, {%1, %1};" : "=l"(ed[7]) : "f"(e1.w));
#pragma unroll
            for (int p = 0; p < 4; p++)
#pragma unroll
                for (int k = 0; k < 8; k++)
                    asm("fma.rn.f32x2 %0, %1, %2, %0;"
                        : "+l"(acc[p][k]) : "l"(zp[p]), "l"(ed[k]));
        }

        // distances + best update (codes ascending within thread -> '<' keeps first)
#pragma unroll
        for (int p = 0; p < 4; p++) {
#pragma unroll
            for (int k = 0; k < 8; k++) {
                float lo, hi;
                asm("mov.b64 {%0, %1}, %2;" : "=f"(lo), "=f"(hi) : "l"(acc[p][k]));
                int kk = kb + tx * 8 + k;
                float wv = ws[tx * 8 + k];
                float d0 = __fadd_rn(__fadd_rn(zq[2*p], wv), __fmul_rn(-2.f, lo));
                float d1 = __fadd_rn(__fadd_rn(zq[2*p+1], wv), __fmul_rn(-2.f, hi));
                if (d0 < bd[2*p])   { bd[2*p] = d0;   bk[2*p] = kk; }
                if (d1 < bd[2*p+1]) { bd[2*p+1] = d1; bk[2*p+1] = kk; }
            }
        }
    }

    // reduce across the 16 tx lanes (tie -> lowest code index)
#pragma unroll
    for (int j = 0; j < 8; j++) {
        float d = bd[j]; int k = bk[j];
#pragma unroll
        for (int off = 8; off; off >>= 1) {
            float od = __shfl_xor_sync(0xffffffffu, d, off, 16);
            int   ok = __shfl_xor_sync(0xffffffffu, k, off, 16);
            if (od < d || (od == d && ok < k)) { d = od; k = ok; }
        }
        if (tx == 0) {
            int t = tb + ty * 8 + j;
            g_pd[t * gridDim.y + blockIdx.y] = d;
            g_pi[t * gridDim.y + blockIdx.y] = k;
        }
    }
}

// ---------------- reduce over K-splits ----------------
__global__ void k_red(int N, int KS) {
    int t = blockIdx.x * 256 + threadIdx.x;
    if (t >= N) return;
    float bd = g_pd[t * KS]; int bk = g_pi[t * KS];
    for (int s = 1; s < KS; s++) {
        float d = g_pd[t * KS + s]; int k = g_pi[t * KS + s];
        if (d < bd || (d == bd && k < bk)) { bd = d; bk = k; }
    }
    g_tok[t] = bk;
}

// ---------------- cubic (jax Keys a=-0.5) weights, renormalized -------------
template<int PN>
__device__ __forceinline__ void cubw(int o, float* w) {
    if (PN == 1) { w[0] = 1.f; return; }
    float s = __fadd_rn(__fmul_rn(__fadd_rn((float)o, 0.5f), (float)PN / 16.f), -0.5f);
    float tot = 0.f;
#pragma unroll
    for (int i = 0; i < PN; i++) {
        float x = fabsf(s - (float)i);
        float v;
        if (x >= 2.f)      v = 0.f;
        else if (x >= 1.f) v = ((-0.5f * x + 2.5f) * x - 4.f) * x + 2.f;
        else               v = ((1.5f * x - 2.5f) * x) * x + 1.f;
        w[i] = v; tot += v;
    }
#pragma unroll
    for (int i = 0; i < PN; i++) w[i] = w[i] / tot;
}

// ---------------- gather + bicubic up + residual update (levels 0..3) -------
template<int PN>
__global__ void __launch_bounds__(256) k_up(const float* __restrict__ emb,
                                            const float* __restrict__ outPrev,
                                            float* __restrict__ outCur,
                                            int isFirst) {
    __shared__ float ew[PN * PN][32];
    int b = blockIdx.x;
    int tid = threadIdx.x;
    for (int idx = tid; idx < PN * PN * 8; idx += 256) {
        int token = idx >> 3, seg = idx & 7;
        int code = g_tok[b * PN * PN + token];
        float4 v = *(const float4*)(emb + code * 32 + seg * 4);
        *(float4*)&ew[token][seg * 4] = v;
    }
    __syncthreads();
    int y = tid >> 4, x = tid & 15;
    float wy[PN], wx[PN];
    cubw<PN>(y, wy);
    cubw<PN>(x, wx);
#pragma unroll
    for (int c = 0; c < 32; c++) {
        float acc = 0.f;
#pragma unroll
        for (int j = 0; j < PN; j++) {
            float tmp = 0.f;
#pragma unroll
            for (int i = 0; i < PN; i++) tmp += wx[i] * ew[j * PN + i][c];
            acc += wy[j] * tmp;
        }
        int idx = (b * 32 + c) * 256 + y * 16 + x;
        float prev = isFirst ? 0.f : outPrev[idx];
        outCur[idx] = prev + acc;
        g_zrest[idx] = g_zrest[idx] - acc;
    }
}

// ---------------- last level: plain gather + accumulate ----------------
__global__ void k_up_last(const float* __restrict__ emb,
                          const float* __restrict__ outPrev,
                          float* __restrict__ outCur) {
    int b = blockIdx.x, tid = threadIdx.x;
    int tok = g_tok[b * 256 + tid];
    const float* e = emb + tok * 32;
#pragma unroll
    for (int c = 0; c < 32; c++) {
        int idx = (b * 32 + c) * 256 + tid;
        outCur[idx] = outPrev[idx] + e[c];
    }
}

extern "C" void kernel_launch(void* const* d_in, const int* in_sizes, int n_in,
                              void* d_out, int out_size) {
    const float* z = (const float*)d_in[0];     // z_enc [64,32,16,16]
    const float* w = (const float*)d_in[1];     // emb_weight [4096,32]
    float* out = (float*)d_out;                 // [5,64,32,16,16]

    k_init<<<NPIX / 256, 256>>>(z);
    k_wsq<<<KK / 256, 256>>>(w);

    const int pns[5]     = {1, 2, 4, 8, 16};
    const int ksplits[5] = {32, 16, 8, 4, 2};

    for (int l = 0; l < 5; l++) {
        int pn = pns[l];
        int N = 64 * pn * pn;
        k_prep<<<N / 8, 256>>>(pn);

        int KS = ksplits[l];
        int codesPerSplit = KK / KS;
        int iters = codesPerSplit / 128;
        dim3 g(N / 64, KS);
        k_dist<<<g, 128>>>(w, codesPerSplit, iters);
        k_red<<<(N + 255) / 256, 256>>>(N, KS);

        float* cur = out + (size_t)l * NPIX;
        const float* prev = (l == 0) ? out : out + (size_t)(l - 1) * NPIX;
        if      (l == 0) k_up<1><<<64, 256>>>(w, prev, cur, 1);
        else if (l == 1) k_up<2><<<64, 256>>>(w, prev, cur, 0);
        else if (l == 2) k_up<4><<<64, 256>>>(w, prev, cur, 0);
        else if (l == 3) k_up<8><<<64, 256>>>(w, prev, cur, 0);
        else             k_up_last<<<64, 256>>>(w, prev, cur);
    }
}